// round 7
// baseline (speedup 1.0000x reference)
#include <cuda_runtime.h>
#include <math.h>

#define NN    50000
#define EE    800000
#define ETOT  (EE + NN)
#define C0    192      // IN_DIM(128) + EMB_DIM(64)
#define IND   128
#define EMBD  64
#define HID   128
#define OUTD  64
#define NG    128

// ---------------- scratch (device globals; no allocation allowed) ----------------
__device__ float    g_h0[NN * C0];       // normalized x ++ emb lookup
__device__ float    g_act[NN * HID];     // layer activations (GEMM input, layers 2+)
__device__ float    g_H[NN * HID];       // h = act @ W
__device__ float    g_as[NN];
__device__ float    g_ad[NN];
__device__ unsigned g_m[NN];             // segment max (order-preserving key)
__device__ float    g_s[NN];             // segment softmax denominator
__device__ int      g_deg[NN];
__device__ int      g_indptr[NN + 1];
__device__ int      g_cursor[NN];
__device__ int      g_csr[ETOT];         // src ids grouped by dst
__device__ float    g_pool[NG * HID];

// ---------------- helpers ----------------
__device__ __forceinline__ unsigned fkey(float f) {
    unsigned b = __float_as_uint(f);
    return (b & 0x80000000u) ? ~b : (b | 0x80000000u);
}
__device__ __forceinline__ float fdecode(unsigned u) {
    unsigned b = (u & 0x80000000u) ? (u & 0x7FFFFFFFu) : ~u;
    return __uint_as_float(b);
}
__device__ __forceinline__ float lrelu2(float x) { return x > 0.f ? x : 0.2f * x; }
__device__ __forceinline__ float geluf(float v) {
    // JAX default gelu (approximate=True, tanh form)
    float t = 0.7978845608028654f * (v + 0.044715f * v * v * v);
    return 0.5f * v * (1.f + tanhf(t));
}

// ---------------- kernels ----------------
__global__ void zero_kernel() {
    int i = blockIdx.x * blockDim.x + threadIdx.x;
    if (i < NN) g_deg[i] = 0;
    if (i < NG * HID) g_pool[i] = 0.f;
}

// warp per node: L2-normalize x row, append embedding
__global__ void prep_kernel(const float* __restrict__ x,
                            const int* __restrict__ node_index,
                            const float* __restrict__ emb) {
    int warp = (blockIdx.x * blockDim.x + threadIdx.x) >> 5;
    int lane = threadIdx.x & 31;
    if (warp >= NN) return;
    float4 v = ((const float4*)(x + (size_t)warp * IND))[lane];
    float ss = v.x * v.x + v.y * v.y + v.z * v.z + v.w * v.w;
    #pragma unroll
    for (int off = 16; off > 0; off >>= 1) ss += __shfl_xor_sync(0xFFFFFFFFu, ss, off);
    float nrm = sqrtf(ss);
    if (nrm == 0.f) nrm = 1e-8f;
    float inv = 1.f / nrm;
    float4 o = make_float4(v.x * inv, v.y * inv, v.z * inv, v.w * inv);
    ((float4*)(g_h0 + (size_t)warp * C0))[lane] = o;
    int vi = node_index[warp];
    if (lane < 16) {
        float4 e = ((const float4*)(emb + (size_t)vi * EMBD))[lane];
        ((float4*)(g_h0 + (size_t)warp * C0 + IND))[lane] = e;
    }
}

__global__ void count_kernel(const int* __restrict__ ei) {
    int e = blockIdx.x * blockDim.x + threadIdx.x;
    if (e >= ETOT) return;
    int d = (e < EE) ? ei[EE + e] : (e - EE);
    atomicAdd(&g_deg[d], 1);
}

// single-block exclusive scan -> indptr, cursor
#define SCAN_NT 1024
#define SCAN_CH 49  // 1024*49 >= 50000
__global__ void scan_kernel() {
    __shared__ int sd[SCAN_NT];
    int t = threadIdx.x;
    int i0 = t * SCAN_CH;
    int i1 = i0 + SCAN_CH; if (i1 > NN) i1 = NN;
    int local = 0;
    for (int i = i0; i < i1; i++) local += g_deg[i];
    sd[t] = local;
    __syncthreads();
    for (int off = 1; off < SCAN_NT; off <<= 1) {
        int v = sd[t];
        int add = (t >= off) ? sd[t - off] : 0;
        __syncthreads();
        sd[t] = v + add;
        __syncthreads();
    }
    int run = sd[t] - local;  // exclusive prefix for this thread's chunk
    for (int i = i0; i < i1; i++) {
        g_indptr[i] = run;
        g_cursor[i] = run;
        run += g_deg[i];
    }
    if (i1 == NN && i0 < NN) g_indptr[NN] = run;
    if (t == 0 && NN == 0) g_indptr[0] = 0;
}

__global__ void scatter_kernel(const int* __restrict__ ei) {
    int e = blockIdx.x * blockDim.x + threadIdx.x;
    if (e >= ETOT) return;
    int s, d;
    if (e < EE) { s = ei[e]; d = ei[EE + e]; }
    else        { s = d = e - EE; }
    int pos = atomicAdd(&g_cursor[d], 1);
    g_csr[pos] = s;
}

// H = A @ W ; A = g_h0 (K=192) or g_act (K=128). BM=64, BN=128, BK=8, 256 thr, 8x4/thread
template <int K>
__global__ void gemm_kernel(const float* __restrict__ W) {
    const float* __restrict__ A = (K == C0) ? g_h0 : g_act;
    __shared__ float As[64][9];
    __shared__ __align__(16) float Bs[8][HID];
    int row0 = blockIdx.x * 64;
    int tid = threadIdx.x;
    int tx = tid & 31, ty = tid >> 5;
    float acc[8][4];
    #pragma unroll
    for (int i = 0; i < 8; i++)
        #pragma unroll
        for (int j = 0; j < 4; j++) acc[i][j] = 0.f;

    for (int k0 = 0; k0 < K; k0 += 8) {
        #pragma unroll
        for (int i = 0; i < 2; i++) {
            int idx = tid * 2 + i;
            int r = idx >> 3, kk = idx & 7;
            int gr = row0 + r;
            As[r][kk] = (gr < NN) ? A[(size_t)gr * K + k0 + kk] : 0.f;
        }
        #pragma unroll
        for (int i = 0; i < 4; i++) {
            int idx = tid + 256 * i;
            int kk = idx >> 7, c = idx & 127;
            Bs[kk][c] = W[(size_t)(k0 + kk) * HID + c];
        }
        __syncthreads();
        #pragma unroll
        for (int kk = 0; kk < 8; kk++) {
            float4 b = ((const float4*)Bs[kk])[tx];
            #pragma unroll
            for (int i = 0; i < 8; i++) {
                float a = As[ty * 8 + i][kk];
                acc[i][0] += a * b.x; acc[i][1] += a * b.y;
                acc[i][2] += a * b.z; acc[i][3] += a * b.w;
            }
        }
        __syncthreads();
    }
    #pragma unroll
    for (int i = 0; i < 8; i++) {
        int r = row0 + ty * 8 + i;
        if (r < NN) {
            float4 v = make_float4(acc[i][0], acc[i][1], acc[i][2], acc[i][3]);
            ((float4*)(g_H + (size_t)r * HID))[tx] = v;
        }
    }
}

// warp per row: as_n = H.a_s, ad_n = H.a_d ; also reset m/s for this layer
__global__ void rowdot_kernel(const float* __restrict__ a_s,
                              const float* __restrict__ a_d) {
    int warp = (blockIdx.x * blockDim.x + threadIdx.x) >> 5;
    int lane = threadIdx.x & 31;
    if (warp >= NN) return;
    float4 h = ((const float4*)g_H)[(size_t)warp * 32 + lane];
    float4 a = ((const float4*)a_s)[lane];
    float4 d = ((const float4*)a_d)[lane];
    float ps = h.x * a.x + h.y * a.y + h.z * a.z + h.w * a.w;
    float pd = h.x * d.x + h.y * d.y + h.z * d.z + h.w * d.w;
    #pragma unroll
    for (int off = 16; off > 0; off >>= 1) {
        ps += __shfl_xor_sync(0xFFFFFFFFu, ps, off);
        pd += __shfl_xor_sync(0xFFFFFFFFu, pd, off);
    }
    if (lane == 0) {
        g_as[warp] = ps;
        g_ad[warp] = pd;
        g_m[warp] = 0u;     // fkey(-huge) sentinel; every node has a self-loop
        g_s[warp] = 0.f;
    }
}

__global__ void edge_max_kernel(const int* __restrict__ ei) {
    int e = blockIdx.x * blockDim.x + threadIdx.x;
    if (e >= ETOT) return;
    int s, d;
    if (e < EE) { s = ei[e]; d = ei[EE + e]; }
    else        { s = d = e - EE; }
    float l = lrelu2(g_as[s] + g_ad[d]);
    atomicMax(&g_m[d], fkey(l));
}

__global__ void edge_sum_kernel(const int* __restrict__ ei) {
    int e = blockIdx.x * blockDim.x + threadIdx.x;
    if (e >= ETOT) return;
    int s, d;
    if (e < EE) { s = ei[e]; d = ei[EE + e]; }
    else        { s = d = e - EE; }
    float l = lrelu2(g_as[s] + g_ad[d]);
    float w = __expf(l - fdecode(g_m[d]));
    atomicAdd(&g_s[d], w);
}

// warp per dst node: out[d] = sum_src coef * H[src]; + bias, gelu -> g_act
__global__ void aggregate_kernel(const float* __restrict__ bias) {
    int warp = (blockIdx.x * blockDim.x + threadIdx.x) >> 5;
    int lane = threadIdx.x & 31;
    if (warp >= NN) return;
    int start = g_indptr[warp], end = g_indptr[warp + 1];
    float adv = g_ad[warp];
    float m = fdecode(g_m[warp]);
    float inv = 1.f / g_s[warp];
    float4 acc = make_float4(0.f, 0.f, 0.f, 0.f);
    for (int j = start; j < end; j++) {
        int s = g_csr[j];                         // uniform across warp -> broadcast
        float l = lrelu2(g_as[s] + adv);
        float c = __expf(l - m) * inv;
        float4 h = ((const float4*)g_H)[(size_t)s * 32 + lane];
        acc.x += h.x * c; acc.y += h.y * c; acc.z += h.z * c; acc.w += h.w * c;
    }
    float4 b = ((const float4*)bias)[lane];
    float4 o;
    o.x = geluf(acc.x + b.x);
    o.y = geluf(acc.y + b.y);
    o.z = geluf(acc.z + b.z);
    o.w = geluf(acc.w + b.w);
    ((float4*)g_act)[(size_t)warp * 32 + lane] = o;
}

// global_add_pool: block handles 128 consecutive nodes, thread = channel.
// batch is sorted, so accumulate locally and flush on graph-id change.
__global__ void pool_kernel(const int* __restrict__ batch) {
    int n0 = blockIdx.x * 128;
    int c = threadIdx.x;
    if (n0 >= NN) return;
    int cur = batch[n0];
    float acc = 0.f;
    for (int i = 0; i < 128; i++) {
        int n = n0 + i;
        if (n >= NN) break;
        int b = batch[n];
        if (b != cur) {
            atomicAdd(&g_pool[cur * HID + c], acc);
            acc = 0.f;
            cur = b;
        }
        acc += g_act[(size_t)n * HID + c];
    }
    atomicAdd(&g_pool[cur * HID + c], acc);
}

__global__ void final_kernel(const float* __restrict__ fcW,
                             const float* __restrict__ fcb,
                             float* __restrict__ out) {
    __shared__ float gr[HID];
    int g = blockIdx.x, c = threadIdx.x;   // 64 threads
    gr[c] = g_pool[g * HID + c];
    gr[c + 64] = g_pool[g * HID + c + 64];
    __syncthreads();
    float acc = fcb[c];
    #pragma unroll
    for (int k = 0; k < HID; k++) acc += gr[k] * fcW[k * OUTD + c];
    float v = acc > 0.f ? acc : 0.01f * acc;
    out[g * OUTD + c] = v;
}

// ---------------- launch ----------------
extern "C" void kernel_launch(void* const* d_in, const int* in_sizes, int n_in,
                              void* d_out, int out_size) {
    const float* x          = (const float*)d_in[0];
    const int*   node_index = (const int*)  d_in[1];
    const int*   edge_index = (const int*)  d_in[2];
    const int*   batch      = (const int*)  d_in[3];
    const float* emb        = (const float*)d_in[4];
    const float* W1  = (const float*)d_in[5];
    const float* a1s = (const float*)d_in[6];
    const float* a1d = (const float*)d_in[7];
    const float* b1  = (const float*)d_in[8];
    const float* W2  = (const float*)d_in[9];
    const float* a2s = (const float*)d_in[10];
    const float* a2d = (const float*)d_in[11];
    const float* b2  = (const float*)d_in[12];
    const float* W3  = (const float*)d_in[13];
    const float* a3s = (const float*)d_in[14];
    const float* a3d = (const float*)d_in[15];
    const float* b3  = (const float*)d_in[16];
    const float* fcW = (const float*)d_in[17];
    const float* fcb = (const float*)d_in[18];
    float* out = (float*)d_out;

    const int gWarp = (NN + 7) / 8;            // warp-per-node kernels, 256 thr
    const int gEdge = (ETOT + 255) / 256;
    const int gGemm = (NN + 63) / 64;

    zero_kernel<<<(NN + 255) / 256, 256>>>();
    prep_kernel<<<gWarp, 256>>>(x, node_index, emb);
    count_kernel<<<gEdge, 256>>>(edge_index);
    scan_kernel<<<1, SCAN_NT>>>();
    scatter_kernel<<<gEdge, 256>>>(edge_index);

    // layer 1 (K=192)
    gemm_kernel<C0><<<gGemm, 256>>>(W1);
    rowdot_kernel<<<gWarp, 256>>>(a1s, a1d);
    edge_max_kernel<<<gEdge, 256>>>(edge_index);
    edge_sum_kernel<<<gEdge, 256>>>(edge_index);
    aggregate_kernel<<<gWarp, 256>>>(b1);

    // layer 2
    gemm_kernel<HID><<<gGemm, 256>>>(W2);
    rowdot_kernel<<<gWarp, 256>>>(a2s, a2d);
    edge_max_kernel<<<gEdge, 256>>>(edge_index);
    edge_sum_kernel<<<gEdge, 256>>>(edge_index);
    aggregate_kernel<<<gWarp, 256>>>(b2);

    // layer 3
    gemm_kernel<HID><<<gGemm, 256>>>(W3);
    rowdot_kernel<<<gWarp, 256>>>(a3s, a3d);
    edge_max_kernel<<<gEdge, 256>>>(edge_index);
    edge_sum_kernel<<<gEdge, 256>>>(edge_index);
    aggregate_kernel<<<gWarp, 256>>>(b3);

    pool_kernel<<<(NN + 127) / 128, 128>>>(batch);
    final_kernel<<<NG, OUTD>>>(fcW, fcb, out);
}

// round 8
// speedup vs baseline: 1.2631x; 1.2631x over previous
#include <cuda_runtime.h>
#include <math.h>

#define NN    50000
#define EE    800000
#define ETOT  (EE + NN)
#define C0    192      // IN_DIM(128) + EMB_DIM(64)
#define IND   128
#define EMBD  64
#define HID   128
#define OUTD  64
#define NG    128

#define PART  512
#define NPART ((NN + PART - 1) / PART)   // 98

// ---------------- scratch (device globals; no allocation allowed) ----------------
__device__ float    g_h0[NN * C0];       // normalized x ++ emb lookup
__device__ float    g_act[NN * HID];     // layer activations (GEMM input, layers 2+)
__device__ float    g_H[NN * HID];       // h = act @ W
__device__ float    g_as[NN];
__device__ float    g_ad[NN];
__device__ int      g_deg[NN];
__device__ int      g_indptr[NN + 1];
__device__ int      g_cursor[NN];
__device__ int      g_csr[ETOT];         // src ids grouped by dst
__device__ float    g_pool[NG * HID];
__device__ int      g_bsum[NPART];
__device__ int      g_boff[NPART];

// ---------------- helpers ----------------
__device__ __forceinline__ float lrelu2(float x) { return x > 0.f ? x : 0.2f * x; }
__device__ __forceinline__ float geluf(float v) {
    // JAX default gelu (approximate=True, tanh form)
    float t = 0.7978845608028654f * (v + 0.044715f * v * v * v);
    return 0.5f * v * (1.f + tanhf(t));
}

// ---------------- kernels ----------------
__global__ void zero_kernel() {
    int i = blockIdx.x * blockDim.x + threadIdx.x;
    if (i < NN) g_deg[i] = 0;
    if (i < NG * HID) g_pool[i] = 0.f;
}

// warp per node: L2-normalize x row, append embedding
__global__ void prep_kernel(const float* __restrict__ x,
                            const int* __restrict__ node_index,
                            const float* __restrict__ emb) {
    int warp = (blockIdx.x * blockDim.x + threadIdx.x) >> 5;
    int lane = threadIdx.x & 31;
    if (warp >= NN) return;
    float4 v = ((const float4*)(x + (size_t)warp * IND))[lane];
    float ss = v.x * v.x + v.y * v.y + v.z * v.z + v.w * v.w;
    #pragma unroll
    for (int off = 16; off > 0; off >>= 1) ss += __shfl_xor_sync(0xFFFFFFFFu, ss, off);
    float nrm = sqrtf(ss);
    if (nrm == 0.f) nrm = 1e-8f;
    float inv = 1.f / nrm;
    float4 o = make_float4(v.x * inv, v.y * inv, v.z * inv, v.w * inv);
    ((float4*)(g_h0 + (size_t)warp * C0))[lane] = o;
    int vi = node_index[warp];
    if (lane < 16) {
        float4 e = ((const float4*)(emb + (size_t)vi * EMBD))[lane];
        ((float4*)(g_h0 + (size_t)warp * C0 + IND))[lane] = e;
    }
}

__global__ void count_kernel(const int* __restrict__ ei) {
    int e = blockIdx.x * blockDim.x + threadIdx.x;
    if (e >= ETOT) return;
    int d = (e < EE) ? ei[EE + e] : (e - EE);
    atomicAdd(&g_deg[d], 1);
}

// ---- parallel 3-phase exclusive scan of g_deg -> g_indptr / g_cursor ----
__global__ void blocksum_kernel() {
    __shared__ int sd[PART];
    int i = blockIdx.x * PART + threadIdx.x;
    sd[threadIdx.x] = (i < NN) ? g_deg[i] : 0;
    __syncthreads();
    #pragma unroll
    for (int off = PART / 2; off > 0; off >>= 1) {
        if (threadIdx.x < off) sd[threadIdx.x] += sd[threadIdx.x + off];
        __syncthreads();
    }
    if (threadIdx.x == 0) g_bsum[blockIdx.x] = sd[0];
}

__global__ void partscan_kernel() {   // 1 block, 128 threads, NPART<=128
    __shared__ int sd[128];
    int t = threadIdx.x;
    int v = (t < NPART) ? g_bsum[t] : 0;
    sd[t] = v;
    __syncthreads();
    for (int off = 1; off < 128; off <<= 1) {
        int x = sd[t];
        int add = (t >= off) ? sd[t - off] : 0;
        __syncthreads();
        sd[t] = x + add;
        __syncthreads();
    }
    if (t < NPART) g_boff[t] = sd[t] - v;   // exclusive
}

__global__ void localscan_kernel() {
    __shared__ int sd[PART];
    int b = blockIdx.x;
    int i = b * PART + threadIdx.x;
    int v = (i < NN) ? g_deg[i] : 0;
    sd[threadIdx.x] = v;
    __syncthreads();
    for (int off = 1; off < PART; off <<= 1) {
        int x = sd[threadIdx.x];
        int add = (threadIdx.x >= (unsigned)off) ? sd[threadIdx.x - off] : 0;
        __syncthreads();
        sd[threadIdx.x] = x + add;
        __syncthreads();
    }
    if (i < NN) {
        int incl = g_boff[b] + sd[threadIdx.x];
        g_indptr[i] = incl - v;
        g_cursor[i] = incl - v;
        if (i == NN - 1) g_indptr[NN] = incl;
    }
}

__global__ void scatter_kernel(const int* __restrict__ ei) {
    int e = blockIdx.x * blockDim.x + threadIdx.x;
    if (e >= ETOT) return;
    int s, d;
    if (e < EE) { s = ei[e]; d = ei[EE + e]; }
    else        { s = d = e - EE; }
    int pos = atomicAdd(&g_cursor[d], 1);
    g_csr[pos] = s;
}

// H = A @ W ; A = g_h0 (K=192) or g_act (K=128). BM=64, BN=128, BK=8, 256 thr, 8x4/thread
// Epilogue: fused per-row dots with a_s / a_d (each warp owns 8 full rows).
template <int K>
__global__ void gemm_kernel(const float* __restrict__ W,
                            const float* __restrict__ a_s,
                            const float* __restrict__ a_d) {
    const float* __restrict__ A = (K == C0) ? g_h0 : g_act;
    __shared__ float As[64][9];
    __shared__ __align__(16) float Bs[8][HID];
    int row0 = blockIdx.x * 64;
    int tid = threadIdx.x;
    int tx = tid & 31, ty = tid >> 5;
    float acc[8][4];
    #pragma unroll
    for (int i = 0; i < 8; i++)
        #pragma unroll
        for (int j = 0; j < 4; j++) acc[i][j] = 0.f;

    for (int k0 = 0; k0 < K; k0 += 8) {
        #pragma unroll
        for (int i = 0; i < 2; i++) {
            int idx = tid * 2 + i;
            int r = idx >> 3, kk = idx & 7;
            int gr = row0 + r;
            As[r][kk] = (gr < NN) ? A[(size_t)gr * K + k0 + kk] : 0.f;
        }
        #pragma unroll
        for (int i = 0; i < 4; i++) {
            int idx = tid + 256 * i;
            int kk = idx >> 7, c = idx & 127;
            Bs[kk][c] = W[(size_t)(k0 + kk) * HID + c];
        }
        __syncthreads();
        #pragma unroll
        for (int kk = 0; kk < 8; kk++) {
            float4 b = ((const float4*)Bs[kk])[tx];
            #pragma unroll
            for (int i = 0; i < 8; i++) {
                float a = As[ty * 8 + i][kk];
                acc[i][0] += a * b.x; acc[i][1] += a * b.y;
                acc[i][2] += a * b.z; acc[i][3] += a * b.w;
            }
        }
        __syncthreads();
    }
    #pragma unroll
    for (int i = 0; i < 8; i++) {
        int r = row0 + ty * 8 + i;
        if (r < NN) {
            float4 v = make_float4(acc[i][0], acc[i][1], acc[i][2], acc[i][3]);
            ((float4*)(g_H + (size_t)r * HID))[tx] = v;
        }
    }
    // fused rowdot epilogue
    float4 avs = ((const float4*)a_s)[tx];
    float4 avd = ((const float4*)a_d)[tx];
    #pragma unroll
    for (int i = 0; i < 8; i++) {
        float ps = acc[i][0] * avs.x + acc[i][1] * avs.y
                 + acc[i][2] * avs.z + acc[i][3] * avs.w;
        float pd = acc[i][0] * avd.x + acc[i][1] * avd.y
                 + acc[i][2] * avd.z + acc[i][3] * avd.w;
        #pragma unroll
        for (int off = 16; off > 0; off >>= 1) {
            ps += __shfl_xor_sync(0xFFFFFFFFu, ps, off);
            pd += __shfl_xor_sync(0xFFFFFFFFu, pd, off);
        }
        int r = row0 + ty * 8 + i;
        if (tx == 0 && r < NN) { g_as[r] = ps; g_ad[r] = pd; }
    }
}

// warp per dst node: online-softmax aggregation (flash style), no edge passes.
__global__ void aggregate_kernel(const float* __restrict__ bias) {
    int warp = (blockIdx.x * blockDim.x + threadIdx.x) >> 5;
    int lane = threadIdx.x & 31;
    if (warp >= NN) return;
    int start = g_indptr[warp], end = g_indptr[warp + 1];
    float adv = g_ad[warp];
    float m = -3.0e38f, sum = 0.f;
    float4 acc = make_float4(0.f, 0.f, 0.f, 0.f);

    int s = g_csr[start];            // every node has a self-loop -> end > start
    float asv = g_as[s];
    for (int j = start; j < end; j++) {
        int jn = j + 1;
        int s2 = (jn < end) ? g_csr[jn] : s;   // prefetch next src + as
        float as2 = g_as[s2];
        float4 h = ((const float4*)g_H)[(size_t)s * 32 + lane];

        float l = lrelu2(asv + adv);
        float mn = fmaxf(m, l);
        float r = __expf(m - mn);
        float w = __expf(l - mn);
        m = mn;
        sum = sum * r + w;
        acc.x = acc.x * r + w * h.x;
        acc.y = acc.y * r + w * h.y;
        acc.z = acc.z * r + w * h.z;
        acc.w = acc.w * r + w * h.w;

        s = s2; asv = as2;
    }
    float inv = 1.f / sum;
    float4 b = ((const float4*)bias)[lane];
    float4 o;
    o.x = geluf(acc.x * inv + b.x);
    o.y = geluf(acc.y * inv + b.y);
    o.z = geluf(acc.z * inv + b.z);
    o.w = geluf(acc.w * inv + b.w);
    ((float4*)g_act)[(size_t)warp * 32 + lane] = o;
}

// global_add_pool: block handles 128 consecutive nodes, thread = channel.
__global__ void pool_kernel(const int* __restrict__ batch) {
    int n0 = blockIdx.x * 128;
    int c = threadIdx.x;
    if (n0 >= NN) return;
    int cur = batch[n0];
    float acc = 0.f;
    for (int i = 0; i < 128; i++) {
        int n = n0 + i;
        if (n >= NN) break;
        int b = batch[n];
        if (b != cur) {
            atomicAdd(&g_pool[cur * HID + c], acc);
            acc = 0.f;
            cur = b;
        }
        acc += g_act[(size_t)n * HID + c];
    }
    atomicAdd(&g_pool[cur * HID + c], acc);
}

__global__ void final_kernel(const float* __restrict__ fcW,
                             const float* __restrict__ fcb,
                             float* __restrict__ out) {
    __shared__ float gr[HID];
    int g = blockIdx.x, c = threadIdx.x;   // 64 threads
    gr[c] = g_pool[g * HID + c];
    gr[c + 64] = g_pool[g * HID + c + 64];
    __syncthreads();
    float acc = fcb[c];
    #pragma unroll
    for (int k = 0; k < HID; k++) acc += gr[k] * fcW[k * OUTD + c];
    float v = acc > 0.f ? acc : 0.01f * acc;
    out[g * OUTD + c] = v;
}

// ---------------- launch ----------------
extern "C" void kernel_launch(void* const* d_in, const int* in_sizes, int n_in,
                              void* d_out, int out_size) {
    const float* x          = (const float*)d_in[0];
    const int*   node_index = (const int*)  d_in[1];
    const int*   edge_index = (const int*)  d_in[2];
    const int*   batch      = (const int*)  d_in[3];
    const float* emb        = (const float*)d_in[4];
    const float* W1  = (const float*)d_in[5];
    const float* a1s = (const float*)d_in[6];
    const float* a1d = (const float*)d_in[7];
    const float* b1  = (const float*)d_in[8];
    const float* W2  = (const float*)d_in[9];
    const float* a2s = (const float*)d_in[10];
    const float* a2d = (const float*)d_in[11];
    const float* b2  = (const float*)d_in[12];
    const float* W3  = (const float*)d_in[13];
    const float* a3s = (const float*)d_in[14];
    const float* a3d = (const float*)d_in[15];
    const float* b3  = (const float*)d_in[16];
    const float* fcW = (const float*)d_in[17];
    const float* fcb = (const float*)d_in[18];
    float* out = (float*)d_out;

    const int gWarp = (NN + 7) / 8;            // warp-per-node kernels, 256 thr
    const int gEdge = (ETOT + 255) / 256;
    const int gGemm = (NN + 63) / 64;

    zero_kernel<<<(NN + 255) / 256, 256>>>();
    prep_kernel<<<gWarp, 256>>>(x, node_index, emb);
    count_kernel<<<gEdge, 256>>>(edge_index);
    blocksum_kernel<<<NPART, PART>>>();
    partscan_kernel<<<1, 128>>>();
    localscan_kernel<<<NPART, PART>>>();
    scatter_kernel<<<gEdge, 256>>>(edge_index);

    // layer 1 (K=192)
    gemm_kernel<C0><<<gGemm, 256>>>(W1, a1s, a1d);
    aggregate_kernel<<<gWarp, 256>>>(b1);

    // layer 2
    gemm_kernel<HID><<<gGemm, 256>>>(W2, a2s, a2d);
    aggregate_kernel<<<gWarp, 256>>>(b2);

    // layer 3
    gemm_kernel<HID><<<gGemm, 256>>>(W3, a3s, a3d);
    aggregate_kernel<<<gWarp, 256>>>(b3);

    pool_kernel<<<(NN + 127) / 128, 128>>>(batch);
    final_kernel<<<NG, OUTD>>>(fcW, fcb, out);
}

// round 12
// speedup vs baseline: 1.3767x; 1.0900x over previous
#include <cuda_runtime.h>
#include <math.h>

#define NN    50000
#define EE    800000
#define ETOT  (EE + NN)
#define C0    192      // IN_DIM(128) + EMB_DIM(64)
#define IND   128
#define EMBD  64
#define HID   128
#define OUTD  64
#define NG    128

#define PART  512
#define NPART ((NN + PART - 1) / PART)   // 98

// ---------------- scratch (device globals; no allocation allowed) ----------------
__device__ float    g_h0[NN * C0];       // normalized x ++ emb lookup
__device__ float    g_act[NN * HID];     // layer activations (GEMM input, layers 2+)
__device__ float    g_H[NN * HID];       // h = act @ W
__device__ float    g_as[NN];
__device__ float    g_ad[NN];
__device__ int      g_deg[NN];
__device__ int      g_indptr[NN + 1];
__device__ int      g_cursor[NN];
__device__ int      g_csr[ETOT];         // src ids grouped by dst
__device__ float    g_pool[NG * HID];
__device__ int      g_bsum[NPART];
__device__ int      g_boff[NPART];

// ---------------- helpers ----------------
__device__ __forceinline__ float lrelu2(float x) { return x > 0.f ? x : 0.2f * x; }
__device__ __forceinline__ float geluf(float v) {
    float t = 0.7978845608028654f * (v + 0.044715f * v * v * v);
    return 0.5f * v * (1.f + tanhf(t));
}
__device__ __forceinline__ void totf32(float v, unsigned& hi, unsigned& lo) {
    asm("cvt.rna.tf32.f32 %0, %1;" : "=r"(hi) : "f"(v));
    float r = v - __uint_as_float(hi);
    asm("cvt.rna.tf32.f32 %0, %1;" : "=r"(lo) : "f"(r));
}
__device__ __forceinline__ void mma8(float* d, const unsigned* a, const unsigned* b) {
    asm volatile(
        "mma.sync.aligned.m16n8k8.row.col.f32.tf32.tf32.f32 "
        "{%0,%1,%2,%3}, {%4,%5,%6,%7}, {%8,%9}, {%0,%1,%2,%3};"
        : "+f"(d[0]), "+f"(d[1]), "+f"(d[2]), "+f"(d[3])
        : "r"(a[0]), "r"(a[1]), "r"(a[2]), "r"(a[3]), "r"(b[0]), "r"(b[1]));
}

// ---------------- kernels ----------------
__global__ void zero_kernel() {
    int i = blockIdx.x * blockDim.x + threadIdx.x;
    if (i < NN) g_deg[i] = 0;
    if (i < NG * HID) g_pool[i] = 0.f;
}

// warp per node: L2-normalize x row, append embedding
__global__ void prep_kernel(const float* __restrict__ x,
                            const int* __restrict__ node_index,
                            const float* __restrict__ emb) {
    int warp = (blockIdx.x * blockDim.x + threadIdx.x) >> 5;
    int lane = threadIdx.x & 31;
    if (warp >= NN) return;
    float4 v = ((const float4*)(x + (size_t)warp * IND))[lane];
    float ss = v.x * v.x + v.y * v.y + v.z * v.z + v.w * v.w;
    #pragma unroll
    for (int off = 16; off > 0; off >>= 1) ss += __shfl_xor_sync(0xFFFFFFFFu, ss, off);
    float nrm = sqrtf(ss);
    if (nrm == 0.f) nrm = 1e-8f;
    float inv = 1.f / nrm;
    float4 o = make_float4(v.x * inv, v.y * inv, v.z * inv, v.w * inv);
    ((float4*)(g_h0 + (size_t)warp * C0))[lane] = o;
    int vi = node_index[warp];
    if (lane < 16) {
        float4 e = ((const float4*)(emb + (size_t)vi * EMBD))[lane];
        ((float4*)(g_h0 + (size_t)warp * C0 + IND))[lane] = e;
    }
}

__global__ void count_kernel(const int* __restrict__ ei) {
    int e = blockIdx.x * blockDim.x + threadIdx.x;
    if (e >= ETOT) return;
    int d = (e < EE) ? ei[EE + e] : (e - EE);
    atomicAdd(&g_deg[d], 1);
}

// ---- parallel 3-phase exclusive scan of g_deg -> g_indptr / g_cursor ----
__global__ void blocksum_kernel() {
    __shared__ int sd[PART];
    int i = blockIdx.x * PART + threadIdx.x;
    sd[threadIdx.x] = (i < NN) ? g_deg[i] : 0;
    __syncthreads();
    #pragma unroll
    for (int off = PART / 2; off > 0; off >>= 1) {
        if (threadIdx.x < off) sd[threadIdx.x] += sd[threadIdx.x + off];
        __syncthreads();
    }
    if (threadIdx.x == 0) g_bsum[blockIdx.x] = sd[0];
}

__global__ void partscan_kernel() {   // 1 block, 128 threads, NPART<=128
    __shared__ int sd[128];
    int t = threadIdx.x;
    int v = (t < NPART) ? g_bsum[t] : 0;
    sd[t] = v;
    __syncthreads();
    for (int off = 1; off < 128; off <<= 1) {
        int x = sd[t];
        int add = (t >= off) ? sd[t - off] : 0;
        __syncthreads();
        sd[t] = x + add;
        __syncthreads();
    }
    if (t < NPART) g_boff[t] = sd[t] - v;   // exclusive
}

__global__ void localscan_kernel() {
    __shared__ int sd[PART];
    int b = blockIdx.x;
    int i = b * PART + threadIdx.x;
    int v = (i < NN) ? g_deg[i] : 0;
    sd[threadIdx.x] = v;
    __syncthreads();
    for (int off = 1; off < PART; off <<= 1) {
        int x = sd[threadIdx.x];
        int add = (threadIdx.x >= (unsigned)off) ? sd[threadIdx.x - off] : 0;
        __syncthreads();
        sd[threadIdx.x] = x + add;
        __syncthreads();
    }
    if (i < NN) {
        int incl = g_boff[b] + sd[threadIdx.x];
        g_indptr[i] = incl - v;
        g_cursor[i] = incl - v;
        if (i == NN - 1) g_indptr[NN] = incl;
    }
}

__global__ void scatter_kernel(const int* __restrict__ ei) {
    int e = blockIdx.x * blockDim.x + threadIdx.x;
    if (e >= ETOT) return;
    int s, d;
    if (e < EE) { s = ei[e]; d = ei[EE + e]; }
    else        { s = d = e - EE; }
    int pos = atomicAdd(&g_cursor[d], 1);
    g_csr[pos] = s;
}

// ---- tensor-core GEMM: H = A @ W via split-tf32 mma.sync (fp32 accuracy) ----
// BM=128, BN=128(=HID), BK=8. 256 threads = 8 warps in 4(m)x2(n); warp tile 32x64.
// Fused epilogue: per-row dots with a_s/a_d via shfl + smem atomics.
template <int K>
__global__ __launch_bounds__(256, 1) void gemm_tc_kernel(const float* __restrict__ W,
                                                         const float* __restrict__ a_s,
                                                         const float* __restrict__ a_d) {
    const float* __restrict__ A = (K == C0) ? g_h0 : g_act;
    __shared__ unsigned As_hi[128][9], As_lo[128][9];
    __shared__ unsigned Bs_hi[8][132], Bs_lo[8][132];
    __shared__ float sps[128], spd[128];

    int tid = threadIdx.x;
    int row0 = blockIdx.x * 128;
    int wid = tid >> 5, lane = tid & 31;
    int warp_m = wid & 3, warp_n = wid >> 2;
    int g = lane >> 2, t4 = lane & 3;

    if (tid < 128) { sps[tid] = 0.f; spd[tid] = 0.f; }

    float d[2][8][4];
    #pragma unroll
    for (int mt = 0; mt < 2; mt++)
        #pragma unroll
        for (int nt = 0; nt < 8; nt++)
            #pragma unroll
            for (int j = 0; j < 4; j++) d[mt][nt][j] = 0.f;

    for (int k0 = 0; k0 < K; k0 += 8) {
        // load + convert A tile (128x8) and B tile (8x128)
        {
            int i0 = tid * 4;
            int am = i0 >> 3, ak = i0 & 7;
            int gr = row0 + am;
            float4 av = make_float4(0.f, 0.f, 0.f, 0.f);
            if (gr < NN) av = *(const float4*)&A[(size_t)gr * K + k0 + ak];
            unsigned h, l;
            totf32(av.x, h, l); As_hi[am][ak + 0] = h; As_lo[am][ak + 0] = l;
            totf32(av.y, h, l); As_hi[am][ak + 1] = h; As_lo[am][ak + 1] = l;
            totf32(av.z, h, l); As_hi[am][ak + 2] = h; As_lo[am][ak + 2] = l;
            totf32(av.w, h, l); As_hi[am][ak + 3] = h; As_lo[am][ak + 3] = l;

            int bk = i0 >> 7, bn = i0 & 127;
            float4 bv = *(const float4*)&W[(size_t)(k0 + bk) * HID + bn];
            totf32(bv.x, h, l); Bs_hi[bk][bn + 0] = h; Bs_lo[bk][bn + 0] = l;
            totf32(bv.y, h, l); Bs_hi[bk][bn + 1] = h; Bs_lo[bk][bn + 1] = l;
            totf32(bv.z, h, l); Bs_hi[bk][bn + 2] = h; Bs_lo[bk][bn + 2] = l;
            totf32(bv.w, h, l); Bs_hi[bk][bn + 3] = h; Bs_lo[bk][bn + 3] = l;
        }
        __syncthreads();

        unsigned a_hi[2][4], a_lo[2][4];
        #pragma unroll
        for (int mt = 0; mt < 2; mt++) {
            int m = warp_m * 32 + mt * 16;
            a_hi[mt][0] = As_hi[m + g][t4];       a_lo[mt][0] = As_lo[m + g][t4];
            a_hi[mt][1] = As_hi[m + g + 8][t4];   a_lo[mt][1] = As_lo[m + g + 8][t4];
            a_hi[mt][2] = As_hi[m + g][t4 + 4];   a_lo[mt][2] = As_lo[m + g][t4 + 4];
            a_hi[mt][3] = As_hi[m + g + 8][t4 + 4]; a_lo[mt][3] = As_lo[m + g + 8][t4 + 4];
        }
        #pragma unroll
        for (int nt = 0; nt < 8; nt++) {
            int n = warp_n * 64 + nt * 8 + g;
            unsigned b_hi[2], b_lo[2];
            b_hi[0] = Bs_hi[t4][n];     b_lo[0] = Bs_lo[t4][n];
            b_hi[1] = Bs_hi[t4 + 4][n]; b_lo[1] = Bs_lo[t4 + 4][n];
            #pragma unroll
            for (int mt = 0; mt < 2; mt++) {
                mma8(d[mt][nt], a_hi[mt], b_hi);
                mma8(d[mt][nt], a_hi[mt], b_lo);
                mma8(d[mt][nt], a_lo[mt], b_hi);
            }
        }
        __syncthreads();
    }

    // store H
    #pragma unroll
    for (int mt = 0; mt < 2; mt++) {
        int r0 = row0 + warp_m * 32 + mt * 16 + g;
        #pragma unroll
        for (int nt = 0; nt < 8; nt++) {
            int col = warp_n * 64 + nt * 8 + 2 * t4;
            if (r0 < NN)
                *(float2*)&g_H[(size_t)r0 * HID + col] = make_float2(d[mt][nt][0], d[mt][nt][1]);
            if (r0 + 8 < NN)
                *(float2*)&g_H[(size_t)(r0 + 8) * HID + col] = make_float2(d[mt][nt][2], d[mt][nt][3]);
        }
    }

    // fused rowdot: ps/pd per row, reduce over 4 lanes then smem atomics
    float ps[2][2] = {{0.f, 0.f}, {0.f, 0.f}};   // [mt][row half]
    float pd[2][2] = {{0.f, 0.f}, {0.f, 0.f}};
    #pragma unroll
    for (int nt = 0; nt < 8; nt++) {
        int col = warp_n * 64 + nt * 8 + 2 * t4;
        float2 avs = *(const float2*)&a_s[col];
        float2 avd = *(const float2*)&a_d[col];
        #pragma unroll
        for (int mt = 0; mt < 2; mt++) {
            ps[mt][0] += d[mt][nt][0] * avs.x + d[mt][nt][1] * avs.y;
            pd[mt][0] += d[mt][nt][0] * avd.x + d[mt][nt][1] * avd.y;
            ps[mt][1] += d[mt][nt][2] * avs.x + d[mt][nt][3] * avs.y;
            pd[mt][1] += d[mt][nt][2] * avd.x + d[mt][nt][3] * avd.y;
        }
    }
    #pragma unroll
    for (int mt = 0; mt < 2; mt++)
        #pragma unroll
        for (int hhalf = 0; hhalf < 2; hhalf++) {
            float s = ps[mt][hhalf], dd = pd[mt][hhalf];
            s += __shfl_xor_sync(0xFFFFFFFFu, s, 1);
            s += __shfl_xor_sync(0xFFFFFFFFu, s, 2);
            dd += __shfl_xor_sync(0xFFFFFFFFu, dd, 1);
            dd += __shfl_xor_sync(0xFFFFFFFFu, dd, 2);
            if (t4 == 0) {
                int r = warp_m * 32 + mt * 16 + hhalf * 8 + g;
                atomicAdd(&sps[r], s);
                atomicAdd(&spd[r], dd);
            }
        }
    __syncthreads();
    if (tid < 128) {
        int r = row0 + tid;
        if (r < NN) { g_as[r] = sps[tid]; g_ad[r] = spd[tid]; }
    }
}

// warp per dst node: online-softmax aggregation (flash style)
__global__ void aggregate_kernel(const float* __restrict__ bias) {
    int warp = (blockIdx.x * blockDim.x + threadIdx.x) >> 5;
    int lane = threadIdx.x & 31;
    if (warp >= NN) return;
    int start = g_indptr[warp], end = g_indptr[warp + 1];
    float adv = g_ad[warp];
    float m = -3.0e38f, sum = 0.f;
    float4 acc = make_float4(0.f, 0.f, 0.f, 0.f);

    int s = g_csr[start];            // every node has a self-loop -> end > start
    float asv = g_as[s];
    for (int j = start; j < end; j++) {
        int jn = j + 1;
        int s2 = (jn < end) ? g_csr[jn] : s;
        float as2 = g_as[s2];
        float4 h = ((const float4*)g_H)[(size_t)s * 32 + lane];

        float l = lrelu2(asv + adv);
        float mn = fmaxf(m, l);
        float r = __expf(m - mn);
        float w = __expf(l - mn);
        m = mn;
        sum = sum * r + w;
        acc.x = acc.x * r + w * h.x;
        acc.y = acc.y * r + w * h.y;
        acc.z = acc.z * r + w * h.z;
        acc.w = acc.w * r + w * h.w;

        s = s2; asv = as2;
    }
    float inv = 1.f / sum;
    float4 b = ((const float4*)bias)[lane];
    float4 o;
    o.x = geluf(acc.x * inv + b.x);
    o.y = geluf(acc.y * inv + b.y);
    o.z = geluf(acc.z * inv + b.z);
    o.w = geluf(acc.w * inv + b.w);
    ((float4*)g_act)[(size_t)warp * 32 + lane] = o;
}

// global_add_pool
__global__ void pool_kernel(const int* __restrict__ batch) {
    int n0 = blockIdx.x * 128;
    int c = threadIdx.x;
    if (n0 >= NN) return;
    int cur = batch[n0];
    float acc = 0.f;
    for (int i = 0; i < 128; i++) {
        int n = n0 + i;
        if (n >= NN) break;
        int b = batch[n];
        if (b != cur) {
            atomicAdd(&g_pool[cur * HID + c], acc);
            acc = 0.f;
            cur = b;
        }
        acc += g_act[(size_t)n * HID + c];
    }
    atomicAdd(&g_pool[cur * HID + c], acc);
}

__global__ void final_kernel(const float* __restrict__ fcW,
                             const float* __restrict__ fcb,
                             float* __restrict__ out) {
    __shared__ float gr[HID];
    int g = blockIdx.x, c = threadIdx.x;   // 64 threads
    gr[c] = g_pool[g * HID + c];
    gr[c + 64] = g_pool[g * HID + c + 64];
    __syncthreads();
    float acc = fcb[c];
    #pragma unroll
    for (int k = 0; k < HID; k++) acc += gr[k] * fcW[k * OUTD + c];
    float v = acc > 0.f ? acc : 0.01f * acc;
    out[g * OUTD + c] = v;
}

// ---------------- launch ----------------
extern "C" void kernel_launch(void* const* d_in, const int* in_sizes, int n_in,
                              void* d_out, int out_size) {
    const float* x          = (const float*)d_in[0];
    const int*   node_index = (const int*)  d_in[1];
    const int*   edge_index = (const int*)  d_in[2];
    const int*   batch      = (const int*)  d_in[3];
    const float* emb        = (const float*)d_in[4];
    const float* W1  = (const float*)d_in[5];
    const float* a1s = (const float*)d_in[6];
    const float* a1d = (const float*)d_in[7];
    const float* b1  = (const float*)d_in[8];
    const float* W2  = (const float*)d_in[9];
    const float* a2s = (const float*)d_in[10];
    const float* a2d = (const float*)d_in[11];
    const float* b2  = (const float*)d_in[12];
    const float* W3  = (const float*)d_in[13];
    const float* a3s = (const float*)d_in[14];
    const float* a3d = (const float*)d_in[15];
    const float* b3  = (const float*)d_in[16];
    const float* fcW = (const float*)d_in[17];
    const float* fcb = (const float*)d_in[18];
    float* out = (float*)d_out;

    const int gWarp = (NN + 7) / 8;
    const int gEdge = (ETOT + 255) / 256;
    const int gGemm = (NN + 127) / 128;    // 391

    zero_kernel<<<(NN + 255) / 256, 256>>>();
    prep_kernel<<<gWarp, 256>>>(x, node_index, emb);
    count_kernel<<<gEdge, 256>>>(edge_index);
    blocksum_kernel<<<NPART, PART>>>();
    partscan_kernel<<<1, 128>>>();
    localscan_kernel<<<NPART, PART>>>();
    scatter_kernel<<<gEdge, 256>>>(edge_index);

    gemm_tc_kernel<C0><<<gGemm, 256>>>(W1, a1s, a1d);
    aggregate_kernel<<<gWarp, 256>>>(b1);

    gemm_tc_kernel<HID><<<gGemm, 256>>>(W2, a2s, a2d);
    aggregate_kernel<<<gWarp, 256>>>(b2);

    gemm_tc_kernel<HID><<<gGemm, 256>>>(W3, a3s, a3d);
    aggregate_kernel<<<gWarp, 256>>>(b3);

    pool_kernel<<<(NN + 127) / 128, 128>>>(batch);
    final_kernel<<<NG, OUTD>>>(fcW, fcb, out);
}